// round 4
// baseline (speedup 1.0000x reference)
#include <cuda_runtime.h>
#include <math.h>

// Problem constants
#define TOK   16384        // B*S
#define DIMH  512          // DIM
#define DIMF  1024         // 2*DIM
#define NS    4096         // NSYM
#define PROJN 32           // PROJ
#define NMAG  8388608ull   // B*S*DIM

#define GSTORE(buf, idx, val, lim) do { size_t _i = (idx); if (_i < (size_t)(lim)) (buf)[_i] = (val); } while (0)

// Scratch (static device globals — no runtime allocation)
__device__ float  g_FLAT[(size_t)TOK * DIMF];      // 64 MiB
__device__ float  g_D[(size_t)TOK * NS];           // 256 MiB: d, then logits, then probs in-place
__device__ float  g_fnorm[TOK];
__device__ float  g_cnorm[NS];
__device__ double g_acc[8];   // 0:sum_mag 1:sum_magsq 2:sum_d 3:sum_sig_meta 4:sum_gate 5:sum_align
__device__ float  g_up;

__device__ __forceinline__ float sigmoidf_(float x) { return 1.0f / (1.0f + expf(-x)); }

// Block reduce (sum of doubles). Safe for repeated calls within a kernel.
__device__ double blockReduceSumD(double v) {
    __shared__ double red[32];
    int lane = threadIdx.x & 31, w = threadIdx.x >> 5;
    #pragma unroll
    for (int o = 16; o > 0; o >>= 1) v += __shfl_down_sync(0xffffffffu, v, o);
    __syncthreads();
    if (lane == 0) red[w] = v;
    __syncthreads();
    double r = (threadIdx.x < (blockDim.x >> 5)) ? red[threadIdx.x] : 0.0;
    if (w == 0) {
        #pragma unroll
        for (int o = 16; o > 0; o >>= 1) r += __shfl_down_sync(0xffffffffu, r, o);
    }
    return r;  // valid in thread 0
}

__global__ void k_zero() { if (threadIdx.x < 8) g_acc[threadIdx.x] = 0.0; }

// Build flat = [z_real, z_imag] per token
__global__ void k_flat(const float* __restrict__ zr, const float* __restrict__ zi) {
    size_t stride = (size_t)gridDim.x * blockDim.x;
    for (size_t i = (size_t)blockIdx.x * blockDim.x + threadIdx.x;
         i < (size_t)TOK * DIMF; i += stride) {
        size_t t = i >> 10; int k = (int)(i & 1023);
        g_FLAT[i] = (k < DIMH) ? zr[t * DIMH + k] : zi[t * DIMH + (k - DIMH)];
    }
}

// Sum of |z| and |z|^2 for batch variance
__global__ void k_magvar(const float* __restrict__ zr, const float* __restrict__ zi) {
    double s = 0.0, s2 = 0.0;
    size_t stride = (size_t)gridDim.x * blockDim.x;
    for (size_t i = (size_t)blockIdx.x * blockDim.x + threadIdx.x; i < NMAG; i += stride) {
        float a = zr[i], b = zi[i];
        float m2 = a * a + b * b;
        s  += (double)sqrtf(m2);
        s2 += (double)m2;
    }
    double r = blockReduceSumD(s);
    if (threadIdx.x == 0) atomicAdd(&g_acc[0], r);
    r = blockReduceSumD(s2);
    if (threadIdx.x == 0) atomicAdd(&g_acc[1], r);
}

__global__ void k_up() {
    double n   = (double)NMAG;
    double var = (g_acc[1] - g_acc[0] * g_acc[0] / n) / (n - 1.0);   // ddof=1
    float  x   = (float)(var / (1.0 + 1e-6));
    g_up = log1pf(expf(x));     // softplus
}

__global__ void k_fnorm() {
    int t = blockIdx.x;
    const float* row = &g_FLAT[(size_t)t * DIMF];
    float s = 0.0f;
    for (int k = threadIdx.x; k < DIMF; k += blockDim.x) { float v = row[k]; s += v * v; }
    double r = blockReduceSumD((double)s);
    if (threadIdx.x == 0) g_fnorm[t] = (float)r;
}

__global__ void k_cnorm(const float* __restrict__ cb) {
    int m = blockIdx.x;
    const float* row = &cb[(size_t)m * DIMF];
    float s = 0.0f;
    for (int k = threadIdx.x; k < DIMF; k += blockDim.x) { float v = row[k]; s += v * v; }
    double r = blockReduceSumD((double)s);
    if (threadIdx.x == 0) g_cnorm[m] = (float)r;
}

// ---------------- Tiled fp32 GEMMs: 64x64 tile, BK=16, 256 threads, 4x4 micro ----------------
#define BM 64
#define BN 64
#define BK 16
#define ASTR 68

// d = fnorm + cnorm - 2 * flat . cb^T  ; store d; accumulate sum(d)
__global__ void __launch_bounds__(256) k_gemm_d(const float* __restrict__ cb) {
    __shared__ float As[BK * ASTR];
    __shared__ float Bs[BK * ASTR];
    int tid = threadIdx.x;
    int tx = tid & 15, ty = tid >> 4;
    int m0 = blockIdx.y * BM, n0 = blockIdx.x * BN;
    int aRow = tid >> 2;
    int aK   = (tid & 3) * 4;
    float acc[4][4] = {};
    for (int k0 = 0; k0 < DIMF; k0 += BK) {
        float4 av = *(const float4*)&g_FLAT[(size_t)(m0 + aRow) * DIMF + k0 + aK];
        float4 bv = *(const float4*)&cb[(size_t)(n0 + aRow) * DIMF + k0 + aK];
        __syncthreads();
        As[(aK+0)*ASTR + aRow] = av.x; As[(aK+1)*ASTR + aRow] = av.y;
        As[(aK+2)*ASTR + aRow] = av.z; As[(aK+3)*ASTR + aRow] = av.w;
        Bs[(aK+0)*ASTR + aRow] = bv.x; Bs[(aK+1)*ASTR + aRow] = bv.y;
        Bs[(aK+2)*ASTR + aRow] = bv.z; Bs[(aK+3)*ASTR + aRow] = bv.w;
        __syncthreads();
        #pragma unroll
        for (int kk = 0; kk < BK; kk++) {
            float4 a = *(const float4*)&As[kk * ASTR + ty * 4];
            float4 b = *(const float4*)&Bs[kk * ASTR + tx * 4];
            float ar[4] = {a.x, a.y, a.z, a.w};
            float br[4] = {b.x, b.y, b.z, b.w};
            #pragma unroll
            for (int i = 0; i < 4; i++)
                #pragma unroll
                for (int j = 0; j < 4; j++) acc[i][j] += ar[i] * br[j];
        }
    }
    float dsum = 0.0f;
    #pragma unroll
    for (int i = 0; i < 4; i++) {
        int r = m0 + ty * 4 + i;
        float fn = g_fnorm[r];
        #pragma unroll
        for (int j = 0; j < 4; j++) {
            int c = n0 + tx * 4 + j;
            float d = fn + g_cnorm[c] - 2.0f * acc[i][j];
            g_D[(size_t)r * NS + c] = d;
            dsum += d;
        }
    }
    double red = blockReduceSumD((double)dsum);
    if (tid == 0) atomicAdd(&g_acc[2], red);
}

// Dual-B GEMM: gb = prev@T, mb = prev@M; epilogue: logits in-place, sum(sigmoid(mb))
__global__ void __launch_bounds__(256) k_gemm_bias(const float* __restrict__ prev,
                                                   const float* __restrict__ Tm,
                                                   const float* __restrict__ Mm) {
    __shared__ float As [BK * ASTR];
    __shared__ float B1s[BK * BN];
    __shared__ float B2s[BK * BN];
    int tid = threadIdx.x;
    int tx = tid & 15, ty = tid >> 4;
    int m0 = blockIdx.y * BM, n0 = blockIdx.x * BN;
    int aRow = tid >> 2, aK = (tid & 3) * 4;
    int bK = tid >> 4, bN = (tid & 15) * 4;
    float acc1[4][4] = {}, acc2[4][4] = {};
    for (int k0 = 0; k0 < NS; k0 += BK) {
        float4 av = *(const float4*)&prev[(size_t)(m0 + aRow) * NS + k0 + aK];
        float4 b1 = *(const float4*)&Tm[(size_t)(k0 + bK) * NS + n0 + bN];
        float4 b2 = *(const float4*)&Mm[(size_t)(k0 + bK) * NS + n0 + bN];
        __syncthreads();
        As[(aK+0)*ASTR + aRow] = av.x; As[(aK+1)*ASTR + aRow] = av.y;
        As[(aK+2)*ASTR + aRow] = av.z; As[(aK+3)*ASTR + aRow] = av.w;
        *(float4*)&B1s[bK * BN + bN] = b1;
        *(float4*)&B2s[bK * BN + bN] = b2;
        __syncthreads();
        #pragma unroll
        for (int kk = 0; kk < BK; kk++) {
            float4 a = *(const float4*)&As[kk * ASTR + ty * 4];
            float4 b = *(const float4*)&B1s[kk * BN + tx * 4];
            float4 c = *(const float4*)&B2s[kk * BN + tx * 4];
            float ar[4] = {a.x, a.y, a.z, a.w};
            float br[4] = {b.x, b.y, b.z, b.w};
            float cr[4] = {c.x, c.y, c.z, c.w};
            #pragma unroll
            for (int i = 0; i < 4; i++)
                #pragma unroll
                for (int j = 0; j < 4; j++) {
                    acc1[i][j] += ar[i] * br[j];
                    acc2[i][j] += ar[i] * cr[j];
                }
        }
    }
    float up = g_up;
    float ssum = 0.0f;
    #pragma unroll
    for (int i = 0; i < 4; i++) {
        int r = m0 + ty * 4 + i;
        #pragma unroll
        for (int j = 0; j < 4; j++) {
            int c = n0 + tx * 4 + j;
            size_t idx = (size_t)r * NS + c;
            float dval  = g_D[idx];
            float logit = -(dval - 0.01f * up * sigmoidf_(acc1[i][j]));
            g_D[idx] = logit;
            ssum += sigmoidf_(acc2[i][j]);
        }
    }
    double red = blockReduceSumD((double)ssum);
    if (tid == 0) atomicAdd(&g_acc[3], red);
}

// z_q = probs @ codebook, PLANAR layout: real plane at off_re, imag plane at off_im.
// If has_imag == 0, imag columns are not stored (harness discards imag).
__global__ void __launch_bounds__(256) k_gemm_zq(const float* __restrict__ cb,
                                                 float* __restrict__ out,
                                                 size_t out_lim,
                                                 size_t off_re, size_t off_im,
                                                 int has_imag) {
    __shared__ float As[BK * ASTR];
    __shared__ float Bs[BK * BN];
    int tid = threadIdx.x;
    int tx = tid & 15, ty = tid >> 4;
    int m0 = blockIdx.y * BM, n0 = blockIdx.x * BN;
    int aRow = tid >> 2, aK = (tid & 3) * 4;
    int bK = tid >> 4, bN = (tid & 15) * 4;
    float acc[4][4] = {};
    for (int k0 = 0; k0 < NS; k0 += BK) {
        float4 av = *(const float4*)&g_D[(size_t)(m0 + aRow) * NS + k0 + aK];
        float4 bv = *(const float4*)&cb[(size_t)(k0 + bK) * DIMF + n0 + bN];
        __syncthreads();
        As[(aK+0)*ASTR + aRow] = av.x; As[(aK+1)*ASTR + aRow] = av.y;
        As[(aK+2)*ASTR + aRow] = av.z; As[(aK+3)*ASTR + aRow] = av.w;
        *(float4*)&Bs[bK * BN + bN] = bv;
        __syncthreads();
        #pragma unroll
        for (int kk = 0; kk < BK; kk++) {
            float4 a = *(const float4*)&As[kk * ASTR + ty * 4];
            float4 b = *(const float4*)&Bs[kk * BN + tx * 4];
            float ar[4] = {a.x, a.y, a.z, a.w};
            float br[4] = {b.x, b.y, b.z, b.w};
            #pragma unroll
            for (int i = 0; i < 4; i++)
                #pragma unroll
                for (int j = 0; j < 4; j++) acc[i][j] += ar[i] * br[j];
        }
    }
    #pragma unroll
    for (int i = 0; i < 4; i++) {
        int r = m0 + ty * 4 + i;
        #pragma unroll
        for (int j = 0; j < 4; j++) {
            int c = n0 + tx * 4 + j;
            float v = acc[i][j];
            if (c < DIMH) {
                GSTORE(out, off_re + (size_t)r * DIMH + c, v, out_lim);
            } else if (has_imag) {
                GSTORE(out, off_im + (size_t)r * DIMH + (c - DIMH), v, out_lim);
            }
        }
    }
}

// Softmax per token: probs -> out and into g_D in-place; entropy, argmax, meta-gate sum.
__global__ void __launch_bounds__(256) k_softmax(const float* __restrict__ prevH,
                                                 float* __restrict__ out,
                                                 size_t out_lim,
                                                 size_t off_soft, size_t off_ent,
                                                 size_t off_hard) {
    __shared__ float row[NS];
    __shared__ float sv[256];
    __shared__ int   si[256];
    int t = blockIdx.x, tid = threadIdx.x;
    float* lg = &g_D[(size_t)t * NS];

    float lmax = -INFINITY; int lidx = 0;
    for (int i = tid; i < NS; i += 256) {
        float v = lg[i];
        row[i] = v;
        if (v > lmax) { lmax = v; lidx = i; }
    }
    sv[tid] = lmax; si[tid] = lidx;
    __syncthreads();
    for (int s = 128; s > 0; s >>= 1) {
        if (tid < s) {
            float v2 = sv[tid + s]; int i2 = si[tid + s];
            if (v2 > sv[tid] || (v2 == sv[tid] && i2 < si[tid])) { sv[tid] = v2; si[tid] = i2; }
        }
        __syncthreads();
    }
    float rmax = sv[0]; int amax = si[0];
    __syncthreads();

    float ls = 0.0f;
    for (int i = tid; i < NS; i += 256) {
        float e = expf(row[i] - rmax);
        row[i] = e;
        ls += e;
    }
    sv[tid] = ls;
    __syncthreads();
    for (int s = 128; s > 0; s >>= 1) { if (tid < s) sv[tid] += sv[tid + s]; __syncthreads(); }
    float inv = 1.0f / sv[0];
    __syncthreads();

    float ent = 0.0f;
    for (int i = tid; i < NS; i += 256) {
        float p = row[i] * inv;
        lg[i] = p;                                          // probs into scratch
        GSTORE(out, off_soft + (size_t)t * NS + i, p, out_lim);
        ent -= p * logf(p + 1e-9f);
    }
    sv[tid] = ent;
    __syncthreads();
    for (int s = 128; s > 0; s >>= 1) { if (tid < s) sv[tid] += sv[tid + s]; __syncthreads(); }
    if (tid == 0) {
        float H = sv[0];
        GSTORE(out, off_ent + t, H, out_lim);
        GSTORE(out, off_hard + t, (float)amax, out_lim);
        float gate = sigmoidf_((fabsf(H - prevH[t]) - 0.5f) * 10.0f);
        atomicAdd(&g_acc[4], (double)gate);
    }
}

// proj = flat@W + b ; anchor = probs@anchors ; accumulate sum((proj-anchor)^2)
__global__ void __launch_bounds__(256) k_align(const float* __restrict__ anchors,
                                               const float* __restrict__ W,
                                               const float* __restrict__ bvec) {
    __shared__ float sA[256], sP[256];
    int t = blockIdx.x, tid = threadIdx.x;
    int p = tid & 31, g = tid >> 5;
    const float* pr = &g_D[(size_t)t * NS];
    const float* fl = &g_FLAT[(size_t)t * DIMF];
    float accA = 0.0f, accP = 0.0f;
    for (int n = g; n < NS; n += 8)  accA += pr[n] * anchors[n * PROJN + p];
    for (int k = g; k < DIMF; k += 8) accP += fl[k] * W[k * PROJN + p];
    sA[tid] = accA; sP[tid] = accP;
    __syncthreads();
    if (tid < 32) {
        float A = 0.0f, P = bvec[tid];
        #pragma unroll
        for (int gg = 0; gg < 8; gg++) { A += sA[gg * 32 + tid]; P += sP[gg * 32 + tid]; }
        float d = P - A;
        double part = (double)(d * d);
        #pragma unroll
        for (int o = 16; o > 0; o >>= 1) part += __shfl_down_sync(0xffffffffu, part, o);
        if (tid == 0) atomicAdd(&g_acc[5], part);
    }
}

__global__ void k_final(float* __restrict__ out, size_t out_lim,
                        size_t off_dmean, size_t off_align, size_t off_trans) {
    if (threadIdx.x == 0) {
        double dmean = g_acc[2] / 67108864.0;
        double msig  = g_acc[3] / 67108864.0;
        double gmean = g_acc[4] / 16384.0;
        GSTORE(out, off_dmean, (float)dmean, out_lim);
        GSTORE(out, off_trans, (float)(gmean * (dmean - msig)), out_lim);
        GSTORE(out, off_align, (float)(g_acc[5] / (16384.0 * 32.0)), out_lim);
    }
}

extern "C" void kernel_launch(void* const* d_in, const int* in_sizes, int n_in,
                              void* d_out, int out_size) {
    const float* zr    = (const float*)d_in[0];
    const float* zi    = (const float*)d_in[1];
    const float* prev  = (const float*)d_in[2];
    const float* prevH = (const float*)d_in[3];
    const float* cb    = (const float*)d_in[4];
    const float* Tm    = (const float*)d_in[5];
    const float* anch  = (const float*)d_in[6];
    const float* W     = (const float*)d_in[7];
    const float* bvec  = (const float*)d_in[8];
    const float* Mm    = (const float*)d_in[9];
    float* out = (float*)d_out;
    size_t lim = (size_t)out_size;

    // Output layout is derived from out_size at runtime:
    //   full (planar complex):  16.7M z_q (re plane + im plane) -> total 83,918,851
    //   real-only (imag dropped by harness cast): 8.4M z_q       -> total 75,530,243
    const size_t ZQ_PLANE = (size_t)TOK * DIMH;         // 8,388,608
    int has_imag = (lim >= 83918851ull) ? 1 : 0;
    size_t off_re   = 0;
    size_t off_im   = ZQ_PLANE;
    size_t zq_total = has_imag ? 2 * ZQ_PLANE : ZQ_PLANE;
    size_t off_soft = zq_total;
    size_t off_hard = off_soft + (size_t)TOK * NS;
    size_t off_dmean= off_hard + TOK;
    size_t off_ent  = off_dmean + 1;
    size_t off_align= off_ent + TOK;
    size_t off_trans= off_align + 1;

    k_zero<<<1, 32>>>();
    k_flat<<<4096, 256>>>(zr, zi);
    k_magvar<<<2048, 256>>>(zr, zi);
    k_up<<<1, 1>>>();
    k_fnorm<<<TOK, 256>>>();
    k_cnorm<<<NS, 256>>>(cb);
    k_gemm_d<<<dim3(NS / BN, TOK / BM), 256>>>(cb);
    k_gemm_bias<<<dim3(NS / BN, TOK / BM), 256>>>(prev, Tm, Mm);
    k_softmax<<<TOK, 256>>>(prevH, out, lim, off_soft, off_ent, off_hard);
    k_gemm_zq<<<dim3(DIMF / BN, TOK / BM), 256>>>(cb, out, lim, off_re, off_im, has_imag);
    k_align<<<TOK, 256>>>(anch, W, bvec);
    k_final<<<1, 32>>>(out, lim, off_dmean, off_align, off_trans);
}

// round 5
// speedup vs baseline: 1.0009x; 1.0009x over previous
#include <cuda_runtime.h>
#include <math.h>

// Problem constants
#define TOK   16384        // B*S
#define DIMH  512          // DIM
#define DIMF  1024         // 2*DIM
#define NS    4096         // NSYM
#define PROJN 32           // PROJ
#define NMAG  8388608ull   // B*S*DIM

#define GSTORE(buf, idx, val, lim) do { size_t _i = (idx); if (_i < (size_t)(lim)) (buf)[_i] = (val); } while (0)

// Scratch (static device globals — no runtime allocation)
__device__ float  g_FLAT[(size_t)TOK * DIMF];      // 64 MiB
__device__ float  g_D[(size_t)TOK * NS];           // 256 MiB: d, then logits, then probs in-place
__device__ float  g_fnorm[TOK];
__device__ float  g_cnorm[NS];
__device__ double g_acc[8];   // 0:sum_mag 1:sum_magsq 2:sum_d 3:sum_sig_meta 4:sum_gate 5:sum_align
__device__ float  g_up;

__device__ __forceinline__ float sigmoidf_(float x) { return 1.0f / (1.0f + expf(-x)); }

// Block reduce (sum of doubles). Safe for repeated calls within a kernel.
__device__ double blockReduceSumD(double v) {
    __shared__ double red[32];
    int lane = threadIdx.x & 31, w = threadIdx.x >> 5;
    #pragma unroll
    for (int o = 16; o > 0; o >>= 1) v += __shfl_down_sync(0xffffffffu, v, o);
    __syncthreads();
    if (lane == 0) red[w] = v;
    __syncthreads();
    double r = (threadIdx.x < (blockDim.x >> 5)) ? red[threadIdx.x] : 0.0;
    if (w == 0) {
        #pragma unroll
        for (int o = 16; o > 0; o >>= 1) r += __shfl_down_sync(0xffffffffu, r, o);
    }
    return r;  // valid in thread 0
}

__global__ void k_zero() { if (threadIdx.x < 8) g_acc[threadIdx.x] = 0.0; }

// Build flat = [z_real, z_imag] per token
__global__ void k_flat(const float* __restrict__ zr, const float* __restrict__ zi) {
    size_t stride = (size_t)gridDim.x * blockDim.x;
    for (size_t i = (size_t)blockIdx.x * blockDim.x + threadIdx.x;
         i < (size_t)TOK * DIMF; i += stride) {
        size_t t = i >> 10; int k = (int)(i & 1023);
        g_FLAT[i] = (k < DIMH) ? zr[t * DIMH + k] : zi[t * DIMH + (k - DIMH)];
    }
}

// Sum of |z| and |z|^2 for batch variance
__global__ void k_magvar(const float* __restrict__ zr, const float* __restrict__ zi) {
    double s = 0.0, s2 = 0.0;
    size_t stride = (size_t)gridDim.x * blockDim.x;
    for (size_t i = (size_t)blockIdx.x * blockDim.x + threadIdx.x; i < NMAG; i += stride) {
        float a = zr[i], b = zi[i];
        float m2 = a * a + b * b;
        s  += (double)sqrtf(m2);
        s2 += (double)m2;
    }
    double r = blockReduceSumD(s);
    if (threadIdx.x == 0) atomicAdd(&g_acc[0], r);
    r = blockReduceSumD(s2);
    if (threadIdx.x == 0) atomicAdd(&g_acc[1], r);
}

__global__ void k_up() {
    double n   = (double)NMAG;
    double var = (g_acc[1] - g_acc[0] * g_acc[0] / n) / (n - 1.0);   // ddof=1
    float  x   = (float)(var / (1.0 + 1e-6));
    g_up = log1pf(expf(x));     // softplus
}

__global__ void k_fnorm() {
    int t = blockIdx.x;
    const float* row = &g_FLAT[(size_t)t * DIMF];
    float s = 0.0f;
    for (int k = threadIdx.x; k < DIMF; k += blockDim.x) { float v = row[k]; s += v * v; }
    double r = blockReduceSumD((double)s);
    if (threadIdx.x == 0) g_fnorm[t] = (float)r;
}

__global__ void k_cnorm(const float* __restrict__ cb) {
    int m = blockIdx.x;
    const float* row = &cb[(size_t)m * DIMF];
    float s = 0.0f;
    for (int k = threadIdx.x; k < DIMF; k += blockDim.x) { float v = row[k]; s += v * v; }
    double r = blockReduceSumD((double)s);
    if (threadIdx.x == 0) g_cnorm[m] = (float)r;
}

// ---------------- Tiled fp32 GEMMs: 64x64 tile, BK=16, 256 threads, 4x4 micro ----------------
#define BM 64
#define BN 64
#define BK 16
#define ASTR 68

// d = fnorm + cnorm - 2 * flat . cb^T  ; store d; accumulate sum(d)
__global__ void __launch_bounds__(256) k_gemm_d(const float* __restrict__ cb) {
    __shared__ float As[BK * ASTR];
    __shared__ float Bs[BK * ASTR];
    int tid = threadIdx.x;
    int tx = tid & 15, ty = tid >> 4;
    int m0 = blockIdx.y * BM, n0 = blockIdx.x * BN;
    int aRow = tid >> 2;
    int aK   = (tid & 3) * 4;
    float acc[4][4] = {};
    for (int k0 = 0; k0 < DIMF; k0 += BK) {
        float4 av = *(const float4*)&g_FLAT[(size_t)(m0 + aRow) * DIMF + k0 + aK];
        float4 bv = *(const float4*)&cb[(size_t)(n0 + aRow) * DIMF + k0 + aK];
        __syncthreads();
        As[(aK+0)*ASTR + aRow] = av.x; As[(aK+1)*ASTR + aRow] = av.y;
        As[(aK+2)*ASTR + aRow] = av.z; As[(aK+3)*ASTR + aRow] = av.w;
        Bs[(aK+0)*ASTR + aRow] = bv.x; Bs[(aK+1)*ASTR + aRow] = bv.y;
        Bs[(aK+2)*ASTR + aRow] = bv.z; Bs[(aK+3)*ASTR + aRow] = bv.w;
        __syncthreads();
        #pragma unroll
        for (int kk = 0; kk < BK; kk++) {
            float4 a = *(const float4*)&As[kk * ASTR + ty * 4];
            float4 b = *(const float4*)&Bs[kk * ASTR + tx * 4];
            float ar[4] = {a.x, a.y, a.z, a.w};
            float br[4] = {b.x, b.y, b.z, b.w};
            #pragma unroll
            for (int i = 0; i < 4; i++)
                #pragma unroll
                for (int j = 0; j < 4; j++) acc[i][j] += ar[i] * br[j];
        }
    }
    float dsum = 0.0f;
    #pragma unroll
    for (int i = 0; i < 4; i++) {
        int r = m0 + ty * 4 + i;
        float fn = g_fnorm[r];
        #pragma unroll
        for (int j = 0; j < 4; j++) {
            int c = n0 + tx * 4 + j;
            float d = fn + g_cnorm[c] - 2.0f * acc[i][j];
            g_D[(size_t)r * NS + c] = d;
            dsum += d;
        }
    }
    double red = blockReduceSumD((double)dsum);
    if (tid == 0) atomicAdd(&g_acc[2], red);
}

// Dual-B GEMM: gb = prev@T, mb = prev@M; epilogue: logits in-place, sum(sigmoid(mb))
__global__ void __launch_bounds__(256) k_gemm_bias(const float* __restrict__ prev,
                                                   const float* __restrict__ Tm,
                                                   const float* __restrict__ Mm) {
    __shared__ float As [BK * ASTR];
    __shared__ float B1s[BK * BN];
    __shared__ float B2s[BK * BN];
    int tid = threadIdx.x;
    int tx = tid & 15, ty = tid >> 4;
    int m0 = blockIdx.y * BM, n0 = blockIdx.x * BN;
    int aRow = tid >> 2, aK = (tid & 3) * 4;
    int bK = tid >> 4, bN = (tid & 15) * 4;
    float acc1[4][4] = {}, acc2[4][4] = {};
    for (int k0 = 0; k0 < NS; k0 += BK) {
        float4 av = *(const float4*)&prev[(size_t)(m0 + aRow) * NS + k0 + aK];
        float4 b1 = *(const float4*)&Tm[(size_t)(k0 + bK) * NS + n0 + bN];
        float4 b2 = *(const float4*)&Mm[(size_t)(k0 + bK) * NS + n0 + bN];
        __syncthreads();
        As[(aK+0)*ASTR + aRow] = av.x; As[(aK+1)*ASTR + aRow] = av.y;
        As[(aK+2)*ASTR + aRow] = av.z; As[(aK+3)*ASTR + aRow] = av.w;
        *(float4*)&B1s[bK * BN + bN] = b1;
        *(float4*)&B2s[bK * BN + bN] = b2;
        __syncthreads();
        #pragma unroll
        for (int kk = 0; kk < BK; kk++) {
            float4 a = *(const float4*)&As[kk * ASTR + ty * 4];
            float4 b = *(const float4*)&B1s[kk * BN + tx * 4];
            float4 c = *(const float4*)&B2s[kk * BN + tx * 4];
            float ar[4] = {a.x, a.y, a.z, a.w};
            float br[4] = {b.x, b.y, b.z, b.w};
            float cr[4] = {c.x, c.y, c.z, c.w};
            #pragma unroll
            for (int i = 0; i < 4; i++)
                #pragma unroll
                for (int j = 0; j < 4; j++) {
                    acc1[i][j] += ar[i] * br[j];
                    acc2[i][j] += ar[i] * cr[j];
                }
        }
    }
    float up = g_up;
    float ssum = 0.0f;
    #pragma unroll
    for (int i = 0; i < 4; i++) {
        int r = m0 + ty * 4 + i;
        #pragma unroll
        for (int j = 0; j < 4; j++) {
            int c = n0 + tx * 4 + j;
            size_t idx = (size_t)r * NS + c;
            float dval  = g_D[idx];
            float logit = -(dval - 0.01f * up * sigmoidf_(acc1[i][j]));
            g_D[idx] = logit;
            ssum += sigmoidf_(acc2[i][j]);
        }
    }
    double red = blockReduceSumD((double)ssum);
    if (tid == 0) atomicAdd(&g_acc[3], red);
}

// z_q = probs @ codebook, PLANAR layout: real plane at off_re, imag plane at off_im.
// If has_imag == 0, imag columns are not stored (harness discards imag).
__global__ void __launch_bounds__(256) k_gemm_zq(const float* __restrict__ cb,
                                                 float* __restrict__ out,
                                                 size_t out_lim,
                                                 size_t off_re, size_t off_im,
                                                 int has_imag) {
    __shared__ float As[BK * ASTR];
    __shared__ float Bs[BK * BN];
    int tid = threadIdx.x;
    int tx = tid & 15, ty = tid >> 4;
    int m0 = blockIdx.y * BM, n0 = blockIdx.x * BN;
    int aRow = tid >> 2, aK = (tid & 3) * 4;
    int bK = tid >> 4, bN = (tid & 15) * 4;
    float acc[4][4] = {};
    for (int k0 = 0; k0 < NS; k0 += BK) {
        float4 av = *(const float4*)&g_D[(size_t)(m0 + aRow) * NS + k0 + aK];
        float4 bv = *(const float4*)&cb[(size_t)(k0 + bK) * DIMF + n0 + bN];
        __syncthreads();
        As[(aK+0)*ASTR + aRow] = av.x; As[(aK+1)*ASTR + aRow] = av.y;
        As[(aK+2)*ASTR + aRow] = av.z; As[(aK+3)*ASTR + aRow] = av.w;
        *(float4*)&Bs[bK * BN + bN] = bv;
        __syncthreads();
        #pragma unroll
        for (int kk = 0; kk < BK; kk++) {
            float4 a = *(const float4*)&As[kk * ASTR + ty * 4];
            float4 b = *(const float4*)&Bs[kk * BN + tx * 4];
            float ar[4] = {a.x, a.y, a.z, a.w};
            float br[4] = {b.x, b.y, b.z, b.w};
            #pragma unroll
            for (int i = 0; i < 4; i++)
                #pragma unroll
                for (int j = 0; j < 4; j++) acc[i][j] += ar[i] * br[j];
        }
    }
    #pragma unroll
    for (int i = 0; i < 4; i++) {
        int r = m0 + ty * 4 + i;
        #pragma unroll
        for (int j = 0; j < 4; j++) {
            int c = n0 + tx * 4 + j;
            float v = acc[i][j];
            if (c < DIMH) {
                GSTORE(out, off_re + (size_t)r * DIMH + c, v, out_lim);
            } else if (has_imag) {
                GSTORE(out, off_im + (size_t)r * DIMH + (c - DIMH), v, out_lim);
            }
        }
    }
}

// Softmax per token: probs -> out and into g_D in-place; entropy, argmax, meta-gate sum.
__global__ void __launch_bounds__(256) k_softmax(const float* __restrict__ prevH,
                                                 float* __restrict__ out,
                                                 size_t out_lim,
                                                 size_t off_soft, size_t off_ent,
                                                 size_t off_hard) {
    __shared__ float row[NS];
    __shared__ float sv[256];
    __shared__ int   si[256];
    int t = blockIdx.x, tid = threadIdx.x;
    float* lg = &g_D[(size_t)t * NS];

    float lmax = -INFINITY; int lidx = 0;
    for (int i = tid; i < NS; i += 256) {
        float v = lg[i];
        row[i] = v;
        if (v > lmax) { lmax = v; lidx = i; }
    }
    sv[tid] = lmax; si[tid] = lidx;
    __syncthreads();
    for (int s = 128; s > 0; s >>= 1) {
        if (tid < s) {
            float v2 = sv[tid + s]; int i2 = si[tid + s];
            if (v2 > sv[tid] || (v2 == sv[tid] && i2 < si[tid])) { sv[tid] = v2; si[tid] = i2; }
        }
        __syncthreads();
    }
    float rmax = sv[0]; int amax = si[0];
    __syncthreads();

    float ls = 0.0f;
    for (int i = tid; i < NS; i += 256) {
        float e = expf(row[i] - rmax);
        row[i] = e;
        ls += e;
    }
    sv[tid] = ls;
    __syncthreads();
    for (int s = 128; s > 0; s >>= 1) { if (tid < s) sv[tid] += sv[tid + s]; __syncthreads(); }
    float inv = 1.0f / sv[0];
    __syncthreads();

    float ent = 0.0f;
    for (int i = tid; i < NS; i += 256) {
        float p = row[i] * inv;
        lg[i] = p;                                          // probs into scratch
        GSTORE(out, off_soft + (size_t)t * NS + i, p, out_lim);
        ent -= p * logf(p + 1e-9f);
    }
    sv[tid] = ent;
    __syncthreads();
    for (int s = 128; s > 0; s >>= 1) { if (tid < s) sv[tid] += sv[tid + s]; __syncthreads(); }
    if (tid == 0) {
        float H = sv[0];
        GSTORE(out, off_ent + t, H, out_lim);
        GSTORE(out, off_hard + t, (float)amax, out_lim);
        float gate = sigmoidf_((fabsf(H - prevH[t]) - 0.5f) * 10.0f);
        atomicAdd(&g_acc[4], (double)gate);
    }
}

// proj = flat@W + b ; anchor = probs@anchors ; accumulate sum((proj-anchor)^2)
__global__ void __launch_bounds__(256) k_align(const float* __restrict__ anchors,
                                               const float* __restrict__ W,
                                               const float* __restrict__ bvec) {
    __shared__ float sA[256], sP[256];
    int t = blockIdx.x, tid = threadIdx.x;
    int p = tid & 31, g = tid >> 5;
    const float* pr = &g_D[(size_t)t * NS];
    const float* fl = &g_FLAT[(size_t)t * DIMF];
    float accA = 0.0f, accP = 0.0f;
    for (int n = g; n < NS; n += 8)  accA += pr[n] * anchors[n * PROJN + p];
    for (int k = g; k < DIMF; k += 8) accP += fl[k] * W[k * PROJN + p];
    sA[tid] = accA; sP[tid] = accP;
    __syncthreads();
    if (tid < 32) {
        float A = 0.0f, P = bvec[tid];
        #pragma unroll
        for (int gg = 0; gg < 8; gg++) { A += sA[gg * 32 + tid]; P += sP[gg * 32 + tid]; }
        float d = P - A;
        double part = (double)(d * d);
        #pragma unroll
        for (int o = 16; o > 0; o >>= 1) part += __shfl_down_sync(0xffffffffu, part, o);
        if (tid == 0) atomicAdd(&g_acc[5], part);
    }
}

__global__ void k_final(float* __restrict__ out, size_t out_lim,
                        size_t off_dmean, size_t off_align, size_t off_trans) {
    if (threadIdx.x == 0) {
        double dmean = g_acc[2] / 67108864.0;
        double msig  = g_acc[3] / 67108864.0;
        double gmean = g_acc[4] / 16384.0;
        GSTORE(out, off_dmean, (float)dmean, out_lim);
        GSTORE(out, off_trans, (float)(gmean * (dmean - msig)), out_lim);
        GSTORE(out, off_align, (float)(g_acc[5] / (16384.0 * 32.0)), out_lim);
    }
}

extern "C" void kernel_launch(void* const* d_in, const int* in_sizes, int n_in,
                              void* d_out, int out_size) {
    const float* zr    = (const float*)d_in[0];
    const float* zi    = (const float*)d_in[1];
    const float* prev  = (const float*)d_in[2];
    const float* prevH = (const float*)d_in[3];
    const float* cb    = (const float*)d_in[4];
    const float* Tm    = (const float*)d_in[5];
    const float* anch  = (const float*)d_in[6];
    const float* W     = (const float*)d_in[7];
    const float* bvec  = (const float*)d_in[8];
    const float* Mm    = (const float*)d_in[9];
    float* out = (float*)d_out;
    size_t lim = (size_t)out_size;

    // Output layout is derived from out_size at runtime:
    //   full (planar complex):  16.7M z_q (re plane + im plane) -> total 83,918,851
    //   real-only (imag dropped by harness cast): 8.4M z_q       -> total 75,530,243
    const size_t ZQ_PLANE = (size_t)TOK * DIMH;         // 8,388,608
    int has_imag = (lim >= 83918851ull) ? 1 : 0;
    size_t off_re   = 0;
    size_t off_im   = ZQ_PLANE;
    size_t zq_total = has_imag ? 2 * ZQ_PLANE : ZQ_PLANE;
    size_t off_soft = zq_total;
    size_t off_hard = off_soft + (size_t)TOK * NS;
    size_t off_dmean= off_hard + TOK;
    size_t off_ent  = off_dmean + 1;
    size_t off_align= off_ent + TOK;
    size_t off_trans= off_align + 1;

    k_zero<<<1, 32>>>();
    k_flat<<<4096, 256>>>(zr, zi);
    k_magvar<<<2048, 256>>>(zr, zi);
    k_up<<<1, 1>>>();
    k_fnorm<<<TOK, 256>>>();
    k_cnorm<<<NS, 256>>>(cb);
    k_gemm_d<<<dim3(NS / BN, TOK / BM), 256>>>(cb);
    k_gemm_bias<<<dim3(NS / BN, TOK / BM), 256>>>(prev, Tm, Mm);
    k_softmax<<<TOK, 256>>>(prevH, out, lim, off_soft, off_ent, off_hard);
    k_gemm_zq<<<dim3(DIMF / BN, TOK / BM), 256>>>(cb, out, lim, off_re, off_im, has_imag);
    k_align<<<TOK, 256>>>(anch, W, bvec);
    k_final<<<1, 32>>>(out, lim, off_dmean, off_align, off_trans);
}